// round 1
// baseline (speedup 1.0000x reference)
#include <cuda_runtime.h>
#include <cstddef>

// ---------------------------------------------------------------------------
// WL2 graph conv layer:
//   XW_{local,filter,neighbor} = X @ W_*          (3x 200k x 128 x 128 fp32 GEMM)
//   msg    = relu(XW_n[ref_a] + XW_n[ref_b] + b_n)   (2M edges)
//   conv   = segment_sum(msg, backref)               (scatter-add)
//   out    = relu(XW_l + XW_f * conv + b)
// ---------------------------------------------------------------------------

#define NMAX 200000
#define UNITS 128
#define MAXELEMS ((size_t)NMAX * UNITS)

__device__ float g_xwl[MAXELEMS];
__device__ float g_xwf[MAXELEMS];
__device__ float g_xwn[MAXELEMS];
__device__ float g_conv[MAXELEMS];

// ---------------------------------------------------------------------------
// Zero the conv accumulator (must be re-zeroed every launch: deterministic)
// ---------------------------------------------------------------------------
__global__ void zero_conv_kernel(int n4) {
    int i = blockIdx.x * blockDim.x + threadIdx.x;
    if (i < n4) {
        reinterpret_cast<float4*>(g_conv)[i] = make_float4(0.f, 0.f, 0.f, 0.f);
    }
}

// ---------------------------------------------------------------------------
// Fused triple GEMM: out[w] = X @ W[w], w = blockIdx.y in {local, filter, nbr}
// Block tile: 128 rows x 128 cols, K looped in chunks of 32 through smem.
// 256 threads, each computes an 8x8 register tile (rows ty*4 / 64+ty*4,
// cols tx*4 / 64+tx*4).
// ---------------------------------------------------------------------------
__global__ __launch_bounds__(256, 2)
void gemm3_kernel(const float* __restrict__ X,
                  const float* __restrict__ Wl,
                  const float* __restrict__ Wf,
                  const float* __restrict__ Wn,
                  int nrows) {
    __shared__ float As[32][128];  // [k][row]
    __shared__ float Bs[32][128];  // [k][col]

    const int w = blockIdx.y;
    const float* __restrict__ W = (w == 0) ? Wl : ((w == 1) ? Wf : Wn);
    float* __restrict__ Out = (w == 0) ? g_xwl : ((w == 1) ? g_xwf : g_xwn);

    const int row_base = blockIdx.x * 128;
    const int tid = threadIdx.x;
    const int tx = tid & 15;   // 0..15  -> cols
    const int ty = tid >> 4;   // 0..15  -> rows

    // A-load assignment: row = tid/2, half (k-offset 0 or 16) = tid&1
    const int lrow = tid >> 1;
    const int lh   = tid & 1;
    const bool rvalid = (row_base + lrow) < nrows;
    const float* xrow = X + (size_t)(row_base + lrow) * 128;

    float acc[8][8];
#pragma unroll
    for (int i = 0; i < 8; i++)
#pragma unroll
        for (int j = 0; j < 8; j++) acc[i][j] = 0.f;

    for (int kk = 0; kk < 128; kk += 32) {
        // Load X chunk (transposed into As[k][row])
#pragma unroll
        for (int i = 0; i < 4; i++) {
            float4 v = make_float4(0.f, 0.f, 0.f, 0.f);
            if (rvalid) v = *reinterpret_cast<const float4*>(xrow + kk + lh * 16 + i * 4);
            const int k0 = lh * 16 + i * 4;
            As[k0 + 0][lrow] = v.x;
            As[k0 + 1][lrow] = v.y;
            As[k0 + 2][lrow] = v.z;
            As[k0 + 3][lrow] = v.w;
        }
        // Load W chunk: Bs[k][col]
#pragma unroll
        for (int i = 0; i < 4; i++) {
            const int k  = (tid >> 5) + i * 8;
            const int c4 = (tid & 31);
            float4 v = *reinterpret_cast<const float4*>(W + (size_t)(kk + k) * 128 + c4 * 4);
            *reinterpret_cast<float4*>(&Bs[k][c4 * 4]) = v;
        }
        __syncthreads();

#pragma unroll
        for (int k = 0; k < 32; k++) {
            float a[8], bf[8];
            *reinterpret_cast<float4*>(a)     = *reinterpret_cast<const float4*>(&As[k][ty * 4]);
            *reinterpret_cast<float4*>(a + 4) = *reinterpret_cast<const float4*>(&As[k][64 + ty * 4]);
            *reinterpret_cast<float4*>(bf)     = *reinterpret_cast<const float4*>(&Bs[k][tx * 4]);
            *reinterpret_cast<float4*>(bf + 4) = *reinterpret_cast<const float4*>(&Bs[k][64 + tx * 4]);
#pragma unroll
            for (int i = 0; i < 8; i++)
#pragma unroll
                for (int j = 0; j < 8; j++) acc[i][j] += a[i] * bf[j];
        }
        __syncthreads();
    }

    // Store 8x8 tile
#pragma unroll
    for (int i = 0; i < 8; i++) {
        const int r = row_base + ((i < 4) ? (ty * 4 + i) : (64 + ty * 4 + (i - 4)));
        if (r < nrows) {
            float4 v0 = make_float4(acc[i][0], acc[i][1], acc[i][2], acc[i][3]);
            float4 v1 = make_float4(acc[i][4], acc[i][5], acc[i][6], acc[i][7]);
            *reinterpret_cast<float4*>(Out + (size_t)r * 128 + tx * 4)      = v0;
            *reinterpret_cast<float4*>(Out + (size_t)r * 128 + 64 + tx * 4) = v1;
        }
    }
}

// ---------------------------------------------------------------------------
// Edge kernel: one warp per edge. Each lane handles 4 consecutive units.
// msg = relu(XW_n[a] + XW_n[b] + b_n); scatter-add into g_conv[backref] with
// vector reduction (red.global.add.v4.f32 — 4x fewer L2 atomic transactions).
// ---------------------------------------------------------------------------
__global__ __launch_bounds__(256)
void edge_kernel(const int* __restrict__ ra,
                 const int* __restrict__ rb,
                 const int* __restrict__ br,
                 const float* __restrict__ bn,
                 int m) {
    const int e = blockIdx.x * 8 + (threadIdx.x >> 5);
    if (e >= m) return;
    const int lane = threadIdx.x & 31;

    const int a = __ldg(ra + e);
    const int b = __ldg(rb + e);
    const int c = __ldg(br + e);

    const float4 va = *reinterpret_cast<const float4*>(g_xwn + (size_t)a * 128 + lane * 4);
    const float4 vb = *reinterpret_cast<const float4*>(g_xwn + (size_t)b * 128 + lane * 4);
    const float4 bb = __ldg(reinterpret_cast<const float4*>(bn) + lane);

    const float x = fmaxf(va.x + vb.x + bb.x, 0.f);
    const float y = fmaxf(va.y + vb.y + bb.y, 0.f);
    const float z = fmaxf(va.z + vb.z + bb.z, 0.f);
    const float w = fmaxf(va.w + vb.w + bb.w, 0.f);

    float* dst = g_conv + (size_t)c * 128 + lane * 4;
    asm volatile("red.global.add.v4.f32 [%0], {%1, %2, %3, %4};"
                 :: "l"(dst), "f"(x), "f"(y), "f"(z), "f"(w)
                 : "memory");
}

// ---------------------------------------------------------------------------
// Epilogue: out = relu(XW_l + XW_f * conv + b)
// ---------------------------------------------------------------------------
__global__ void final_kernel(const float* __restrict__ b,
                             float* __restrict__ out,
                             int n4) {
    const int i = blockIdx.x * blockDim.x + threadIdx.x;
    if (i >= n4) return;
    const int c4 = i & 31;  // float4 column within row (128/4 = 32)

    const float4 vl = reinterpret_cast<const float4*>(g_xwl)[i];
    const float4 vf = reinterpret_cast<const float4*>(g_xwf)[i];
    const float4 vc = reinterpret_cast<const float4*>(g_conv)[i];
    const float4 vb = __ldg(reinterpret_cast<const float4*>(b) + c4);

    float4 r;
    r.x = fmaxf(fmaf(vf.x, vc.x, vl.x) + vb.x, 0.f);
    r.y = fmaxf(fmaf(vf.y, vc.y, vl.y) + vb.y, 0.f);
    r.z = fmaxf(fmaf(vf.z, vc.z, vl.z) + vb.z, 0.f);
    r.w = fmaxf(fmaf(vf.w, vc.w, vl.w) + vb.w, 0.f);
    reinterpret_cast<float4*>(out)[i] = r;
}

// ---------------------------------------------------------------------------
extern "C" void kernel_launch(void* const* d_in, const int* in_sizes, int n_in,
                              void* d_out, int out_size) {
    const float* X  = (const float*)d_in[0];
    const int*   ra = (const int*)d_in[1];
    const int*   rb = (const int*)d_in[2];
    const int*   br = (const int*)d_in[3];
    const float* Wl = (const float*)d_in[4];
    const float* Wf = (const float*)d_in[5];
    const float* Wn = (const float*)d_in[6];
    const float* b  = (const float*)d_in[7];
    const float* bn = (const float*)d_in[8];
    float* out = (float*)d_out;

    const int n  = in_sizes[0] / 128;  // 200000 rows
    const int m  = in_sizes[1];        // 2000000 edges
    const int n4 = n * 32;             // float4 count per array

    zero_conv_kernel<<<(n4 + 255) / 256, 256>>>(n4);

    dim3 ggrid((n + 127) / 128, 3);
    gemm3_kernel<<<ggrid, 256>>>(X, Wl, Wf, Wn, n);

    edge_kernel<<<(m + 7) / 8, 256>>>(ra, rb, br, bn, m);

    final_kernel<<<(n4 + 255) / 256, 256>>>(b, out, n4);
}

// round 4
// speedup vs baseline: 1.1740x; 1.1740x over previous
#include <cuda_runtime.h>
#include <cstdint>
#include <cstddef>

// ---------------------------------------------------------------------------
// WL2 graph conv layer — tf32 mma.sync edition (generic PTX, no 'a' features):
//   Phase 0: transpose+tf32-round W's; zero conv accumulator
//   Phase 1: XW_n = X @ W_n               (mma.sync tf32 -> g_xwn)
//   Phase 2: edge gather/relu/scatter     (red.global.add.v4.f32 -> g_conv)
//   Phase 3: out = relu(X@W_l + (X@W_f)*conv + b)  (dual-GEMM fused epilogue)
// ---------------------------------------------------------------------------

#define NMAX 200000
#define MAXELEMS ((size_t)NMAX * 128)

__device__ float g_xwn[MAXELEMS];
__device__ float g_conv[MAXELEMS];
__device__ float g_wt[3 * 128 * 128];   // W^T (K-major), tf32-rounded

// ---------------- helpers ----------------
__device__ __forceinline__ uint32_t f2tf32(float x) {
    uint32_t r;
    asm("cvt.rna.tf32.f32 %0, %1;" : "=r"(r) : "f"(x));
    return r;
}

__device__ __forceinline__ void mma_tf32(float* c,
                                         uint32_t a0, uint32_t a1, uint32_t a2, uint32_t a3,
                                         uint32_t b0, uint32_t b1) {
    asm volatile(
        "mma.sync.aligned.m16n8k8.row.col.f32.tf32.tf32.f32 "
        "{%0,%1,%2,%3}, {%4,%5,%6,%7}, {%8,%9}, {%0,%1,%2,%3};"
        : "+f"(c[0]), "+f"(c[1]), "+f"(c[2]), "+f"(c[3])
        : "r"(a0), "r"(a1), "r"(a2), "r"(a3), "r"(b0), "r"(b1));
}

// Padded smem tile: 128 rows x 132 floats. Fragment LDS bank = lane (conflict-free).
#define TPITCH 132
#define TILE_FLOATS (128 * TPITCH)   // 16896 floats = 67584 B

// ---------------------------------------------------------------------------
// Phase 0a: W^T + tf32 rounding
// ---------------------------------------------------------------------------
__global__ void prep_w_kernel(const float* __restrict__ Wl,
                              const float* __restrict__ Wf,
                              const float* __restrict__ Wn) {
    const float* src = (blockIdx.x == 0) ? Wl : ((blockIdx.x == 1) ? Wf : Wn);
    float* dst = g_wt + blockIdx.x * 16384;
    for (int i = threadIdx.x; i < 16384; i += blockDim.x) {
        int n = i >> 7, k = i & 127;
        dst[i] = __uint_as_float(f2tf32(src[k * 128 + n]));
    }
}

// ---------------------------------------------------------------------------
// Phase 0b: zero conv accumulator
// ---------------------------------------------------------------------------
__global__ void zero_conv_kernel(int n4) {
    int i = blockIdx.x * blockDim.x + threadIdx.x;
    if (i < n4) reinterpret_cast<float4*>(g_conv)[i] = make_float4(0.f, 0.f, 0.f, 0.f);
}

// ---------------------------------------------------------------------------
// Tile loaders (512 threads): A from X (with tf32 rounding), B from g_wt.
// ---------------------------------------------------------------------------
__device__ __forceinline__ void load_a_tile(float* As, const float* __restrict__ X,
                                            int row_base, int nrows, int tid) {
    for (int i = tid; i < 4096; i += 512) {
        const int r = i >> 5, c4 = i & 31;
        float4 v = make_float4(0.f, 0.f, 0.f, 0.f);
        if (row_base + r < nrows)
            v = reinterpret_cast<const float4*>(X)[(size_t)(row_base + r) * 32 + c4];
        v.x = __uint_as_float(f2tf32(v.x));
        v.y = __uint_as_float(f2tf32(v.y));
        v.z = __uint_as_float(f2tf32(v.z));
        v.w = __uint_as_float(f2tf32(v.w));
        *reinterpret_cast<float4*>(&As[r * TPITCH + c4 * 4]) = v;
    }
}

__device__ __forceinline__ void load_b_tile(float* Bs, const float* __restrict__ Wt,
                                            int tid) {
    for (int i = tid; i < 4096; i += 512) {
        const int r = i >> 5, c4 = i & 31;
        float4 v = reinterpret_cast<const float4*>(Wt)[i];
        *reinterpret_cast<float4*>(&Bs[r * TPITCH + c4 * 4]) = v;
    }
}

// ---------------------------------------------------------------------------
// Phase 1: XW_n = X @ W_n.  512 threads; warp tile 16 rows x 64 cols.
// ---------------------------------------------------------------------------
__global__ __launch_bounds__(512, 1)
void gemm_xwn_kernel(const float* __restrict__ X, int nrows) {
    extern __shared__ __align__(16) float smem[];
    float* As = smem;
    float* Bs = smem + TILE_FLOATS;

    const int tid = threadIdx.x;
    const int row_base = blockIdx.x * 128;

    load_a_tile(As, X, row_base, nrows, tid);
    load_b_tile(Bs, g_wt + 2 * 16384, tid);
    __syncthreads();

    const int wid = tid >> 5, lane = tid & 31;
    const int g = lane >> 2, t = lane & 3;
    const int m_base = (wid & 7) * 16;
    const int n_base = (wid >> 3) * 64;

    float acc[8][4];
#pragma unroll
    for (int nt = 0; nt < 8; nt++)
#pragma unroll
        for (int j = 0; j < 4; j++) acc[nt][j] = 0.f;

    const float* ar0 = &As[(m_base + g) * TPITCH + t];
    const float* ar1 = &As[(m_base + 8 + g) * TPITCH + t];
    const float* br  = &Bs[(n_base + g) * TPITCH + t];

#pragma unroll
    for (int ks = 0; ks < 16; ks++) {
        const int k = ks * 8;
        const uint32_t a0 = __float_as_uint(ar0[k]);
        const uint32_t a1 = __float_as_uint(ar1[k]);
        const uint32_t a2 = __float_as_uint(ar0[k + 4]);
        const uint32_t a3 = __float_as_uint(ar1[k + 4]);
#pragma unroll
        for (int nt = 0; nt < 8; nt++) {
            const uint32_t b0 = __float_as_uint(br[nt * 8 * TPITCH + k]);
            const uint32_t b1 = __float_as_uint(br[nt * 8 * TPITCH + k + 4]);
            mma_tf32(acc[nt], a0, a1, a2, a3, b0, b1);
        }
    }

    const int r0 = row_base + m_base + g;
    const int r1 = r0 + 8;
#pragma unroll
    for (int nt = 0; nt < 8; nt++) {
        const int col = n_base + nt * 8 + 2 * t;
        if (r0 < nrows)
            *reinterpret_cast<float2*>(g_xwn + (size_t)r0 * 128 + col) =
                make_float2(acc[nt][0], acc[nt][1]);
        if (r1 < nrows)
            *reinterpret_cast<float2*>(g_xwn + (size_t)r1 * 128 + col) =
                make_float2(acc[nt][2], acc[nt][3]);
    }
}

// ---------------------------------------------------------------------------
// Phase 2: edge gather/relu/scatter. One warp per edge, lane = 4 units.
// ---------------------------------------------------------------------------
__global__ __launch_bounds__(256)
void edge_kernel(const int* __restrict__ ra, const int* __restrict__ rb,
                 const int* __restrict__ br, const float* __restrict__ bn, int m) {
    const int e = blockIdx.x * 8 + (threadIdx.x >> 5);
    if (e >= m) return;
    const int lane = threadIdx.x & 31;

    const int a = __ldg(ra + e);
    const int b = __ldg(rb + e);
    const int c = __ldg(br + e);

    const float4 va = *reinterpret_cast<const float4*>(g_xwn + (size_t)a * 128 + lane * 4);
    const float4 vb = *reinterpret_cast<const float4*>(g_xwn + (size_t)b * 128 + lane * 4);
    const float4 bb = __ldg(reinterpret_cast<const float4*>(bn) + lane);

    const float x = fmaxf(va.x + vb.x + bb.x, 0.f);
    const float y = fmaxf(va.y + vb.y + bb.y, 0.f);
    const float z = fmaxf(va.z + vb.z + bb.z, 0.f);
    const float w = fmaxf(va.w + vb.w + bb.w, 0.f);

    float* dst = g_conv + (size_t)c * 128 + lane * 4;
    asm volatile("red.global.add.v4.f32 [%0], {%1, %2, %3, %4};"
                 :: "l"(dst), "f"(x), "f"(y), "f"(z), "f"(w) : "memory");
}

// ---------------------------------------------------------------------------
// Phase 3: fused final: dual GEMM (W_local, W_filter) + epilogue.
// out = relu(Dl + Df * conv + b)
// ---------------------------------------------------------------------------
__global__ __launch_bounds__(512, 1)
void gemm_final_kernel(const float* __restrict__ X, const float* __restrict__ b,
                       float* __restrict__ out, int nrows) {
    extern __shared__ __align__(16) float smem[];
    float* As  = smem;
    float* Bsl = smem + TILE_FLOATS;
    float* Bsf = smem + 2 * TILE_FLOATS;

    const int tid = threadIdx.x;
    const int row_base = blockIdx.x * 128;

    load_a_tile(As, X, row_base, nrows, tid);
    load_b_tile(Bsl, g_wt + 0 * 16384, tid);
    load_b_tile(Bsf, g_wt + 1 * 16384, tid);
    __syncthreads();

    const int wid = tid >> 5, lane = tid & 31;
    const int g = lane >> 2, t = lane & 3;
    const int m_base = (wid & 7) * 16;
    const int n_base = (wid >> 3) * 64;

    float accl[8][4], accf[8][4];
#pragma unroll
    for (int nt = 0; nt < 8; nt++)
#pragma unroll
        for (int j = 0; j < 4; j++) { accl[nt][j] = 0.f; accf[nt][j] = 0.f; }

    const float* ar0 = &As[(m_base + g) * TPITCH + t];
    const float* ar1 = &As[(m_base + 8 + g) * TPITCH + t];
    const float* brl = &Bsl[(n_base + g) * TPITCH + t];
    const float* brf = &Bsf[(n_base + g) * TPITCH + t];

#pragma unroll
    for (int ks = 0; ks < 16; ks++) {
        const int k = ks * 8;
        const uint32_t a0 = __float_as_uint(ar0[k]);
        const uint32_t a1 = __float_as_uint(ar1[k]);
        const uint32_t a2 = __float_as_uint(ar0[k + 4]);
        const uint32_t a3 = __float_as_uint(ar1[k + 4]);
#pragma unroll
        for (int nt = 0; nt < 8; nt++) {
            const uint32_t bl0 = __float_as_uint(brl[nt * 8 * TPITCH + k]);
            const uint32_t bl1 = __float_as_uint(brl[nt * 8 * TPITCH + k + 4]);
            mma_tf32(accl[nt], a0, a1, a2, a3, bl0, bl1);
            const uint32_t bf0 = __float_as_uint(brf[nt * 8 * TPITCH + k]);
            const uint32_t bf1 = __float_as_uint(brf[nt * 8 * TPITCH + k + 4]);
            mma_tf32(accf[nt], a0, a1, a2, a3, bf0, bf1);
        }
    }

    const int r0 = row_base + m_base + g;
    const int r1 = r0 + 8;
#pragma unroll
    for (int nt = 0; nt < 8; nt++) {
        const int col = n_base + nt * 8 + 2 * t;
        const float2 b2 = __ldg(reinterpret_cast<const float2*>(b + col));
        if (r0 < nrows) {
            const float2 cv = *reinterpret_cast<const float2*>(g_conv + (size_t)r0 * 128 + col);
            float2 o;
            o.x = fmaxf(fmaf(accf[nt][0], cv.x, accl[nt][0]) + b2.x, 0.f);
            o.y = fmaxf(fmaf(accf[nt][1], cv.y, accl[nt][1]) + b2.y, 0.f);
            *reinterpret_cast<float2*>(out + (size_t)r0 * 128 + col) = o;
        }
        if (r1 < nrows) {
            const float2 cv = *reinterpret_cast<const float2*>(g_conv + (size_t)r1 * 128 + col);
            float2 o;
            o.x = fmaxf(fmaf(accf[nt][2], cv.x, accl[nt][2]) + b2.x, 0.f);
            o.y = fmaxf(fmaf(accf[nt][3], cv.y, accl[nt][3]) + b2.y, 0.f);
            *reinterpret_cast<float2*>(out + (size_t)r1 * 128 + col) = o;
        }
    }
}

// ---------------------------------------------------------------------------
extern "C" void kernel_launch(void* const* d_in, const int* in_sizes, int n_in,
                              void* d_out, int out_size) {
    const float* X  = (const float*)d_in[0];
    const int*   ra = (const int*)d_in[1];
    const int*   rb = (const int*)d_in[2];
    const int*   br = (const int*)d_in[3];
    const float* Wl = (const float*)d_in[4];
    const float* Wf = (const float*)d_in[5];
    const float* Wn = (const float*)d_in[6];
    const float* b  = (const float*)d_in[7];
    const float* bn = (const float*)d_in[8];
    float* out = (float*)d_out;

    const int n  = in_sizes[0] / 128;   // 200000
    const int m  = in_sizes[1];         // 2000000
    const int n4 = n * 32;
    const int ntiles = (n + 127) / 128;

    const int smem_a = 2 * TILE_FLOATS * 4;   // 135168 B
    const int smem_c = 3 * TILE_FLOATS * 4;   // 202752 B

    static bool attr_done = false;
    if (!attr_done) {
        cudaFuncSetAttribute(gemm_xwn_kernel,
                             cudaFuncAttributeMaxDynamicSharedMemorySize, smem_a);
        cudaFuncSetAttribute(gemm_final_kernel,
                             cudaFuncAttributeMaxDynamicSharedMemorySize, smem_c);
        attr_done = true;
    }

    prep_w_kernel<<<3, 256>>>(Wl, Wf, Wn);
    zero_conv_kernel<<<(n4 + 255) / 256, 256>>>(n4);
    gemm_xwn_kernel<<<ntiles, 512, smem_a>>>(X, n);
    edge_kernel<<<(m + 7) / 8, 256>>>(ra, rb, br, bn, m);
    gemm_final_kernel<<<ntiles, 512, smem_c>>>(X, b, out, n);
}